// round 12
// baseline (speedup 1.0000x reference)
#include <cuda_runtime.h>
#include <cuda_fp16.h>
#include <cstdint>

#define Bc 32
#define Nn 1024
#define INP 256
#define Hh 8
#define Dd 32
#define INNER 256
#define OUP 256
#define QKVC 768
#define NTOK (Bc * Nn)

#define LOG2E 1.4426950408889634f
#define ONES_H2 0x3C003C00u     // half2(1.0, 1.0)

// ---------------------------------------------------------------------------
// Device-global scratch (fp16 hi/lo)
// ---------------------------------------------------------------------------
__device__ __half g_xh[NTOK * INP],  g_xl[NTOK * INP];
__device__ __half g_wqh[QKVC * INP], g_wql[QKVC * INP];      // W_qkv^T [n][k]
__device__ __half g_woh[OUP * INNER], g_wol[OUP * INNER];    // W_out^T [n][k]
__device__ __half g_qh[Bc*Hh*Nn*Dd];                         // [b,h,n,d] *scale*log2e
__device__ __half g_kh[Bc*Hh*Nn*Dd];                         // hi only (S is 1-term)
__device__ __half g_vth[Bc*Hh*Dd*Nn], g_vtl[Bc*Hh*Dd*Nn];    // [b,h,d,n]
__device__ __half g_oh[NTOK * INNER];                        // attn out, hi only
__device__ __half g_bias[Hh * Nn * Nn];                      // [h][i][j] * log2e

// ---------------------------------------------------------------------------
// Helpers
// ---------------------------------------------------------------------------
__device__ __forceinline__ uint32_t packh(float x, float y) {
    __half2 t = __floats2half2_rn(x, y);
    return *reinterpret_cast<uint32_t*>(&t);
}
__device__ __forceinline__ float2 unpackh(uint32_t u) {
    __half2 t = *reinterpret_cast<__half2*>(&u);
    return __half22float2(t);
}
__device__ __forceinline__ uint32_t hadd2u(uint32_t a, uint32_t b) {
    uint32_t d;
    asm("add.f16x2 %0, %1, %2;" : "=r"(d) : "r"(a), "r"(b));
    return d;
}
__device__ __forceinline__ uint32_t ex2h2(uint32_t a) {
    uint32_t d;
    asm("ex2.approx.f16x2 %0, %1;" : "=r"(d) : "r"(a));
    return d;
}
__device__ __forceinline__ void mma4(float* c, const uint32_t* a, uint32_t b0, uint32_t b1) {
    asm volatile(
        "mma.sync.aligned.m16n8k16.row.col.f32.f16.f16.f32 "
        "{%0,%1,%2,%3}, {%4,%5,%6,%7}, {%8,%9}, {%0,%1,%2,%3};\n"
        : "+f"(c[0]), "+f"(c[1]), "+f"(c[2]), "+f"(c[3])
        : "r"(a[0]), "r"(a[1]), "r"(a[2]), "r"(a[3]), "r"(b0), "r"(b1));
}
__device__ __forceinline__ void ldsm4(uint32_t& r0, uint32_t& r1, uint32_t& r2,
                                      uint32_t& r3, const void* p) {
    uint32_t a = (uint32_t)__cvta_generic_to_shared(p);
    asm volatile("ldmatrix.sync.aligned.m8n8.x4.shared.b16 {%0,%1,%2,%3}, [%4];"
                 : "=r"(r0), "=r"(r1), "=r"(r2), "=r"(r3) : "r"(a));
}
__device__ __forceinline__ void cpa16(void* dst, const void* src) {
    uint32_t d = (uint32_t)__cvta_generic_to_shared(dst);
    asm volatile("cp.async.cg.shared.global [%0], [%1], 16;" :: "r"(d), "l"(src));
}
#define CP_COMMIT asm volatile("cp.async.commit_group;")
#define CP_WAIT0  asm volatile("cp.async.wait_group 0;")

// ---------------------------------------------------------------------------
// Merged prep kernel:
//   blocks [0, 8192)      : x split
//   blocks [8192, 8960)   : W_qkv^T split
//   blocks [8960, 9216)   : W_out^T split
//   blocks [9216, 10240)  : bias gather * log2e
// ---------------------------------------------------------------------------
__global__ void __launch_bounds__(256) prep_all(
    const float* __restrict__ x, const float* __restrict__ wq,
    const float* __restrict__ wo, const float* __restrict__ table,
    const int* __restrict__ rel_index)
{
    const int bid = blockIdx.x;
    if (bid < 8192) {
        size_t i = (size_t)bid * 256 + threadIdx.x;
        float4 v = ((const float4*)x)[i];
        uint32_t h01 = packh(v.x, v.y), h23 = packh(v.z, v.w);
        float2 a = unpackh(h01), b = unpackh(h23);
        ((uint2*)g_xh)[i] = make_uint2(h01, h23);
        ((uint2*)g_xl)[i] = make_uint2(packh(v.x - a.x, v.y - a.y),
                                       packh(v.z - b.x, v.w - b.y));
    } else if (bid < 8960) {
        int i = (bid - 8192) * 256 + threadIdx.x;
        int k = i / QKVC, n = i % QKVC;
        float v = wq[i];
        __half h = __float2half_rn(v);
        g_wqh[n * INP + k] = h;
        g_wql[n * INP + k] = __float2half_rn(v - __half2float(h));
    } else if (bid < 9216) {
        int i = (bid - 8960) * 256 + threadIdx.x;
        int k = i >> 8, n = i & 255;
        float v = wo[i];
        __half h = __float2half_rn(v);
        g_woh[n * INNER + k] = h;
        g_wol[n * INNER + k] = __float2half_rn(v - __half2float(h));
    } else {
        int tI = (bid - 9216) * 256 + threadIdx.x;
        int i = tI >> 8;
        int j = (tI & 255) * 4;
        int4 idx = *(const int4*)&rel_index[i * Nn + j];
        int id[4] = {idx.x, idx.y, idx.z, idx.w};
        float vals[4][8];
        #pragma unroll
        for (int jj = 0; jj < 4; jj++) {
            const float4* tp = (const float4*)(table + (size_t)id[jj] * 8);
            float4 a = tp[0], b = tp[1];
            vals[jj][0] = a.x; vals[jj][1] = a.y; vals[jj][2] = a.z; vals[jj][3] = a.w;
            vals[jj][4] = b.x; vals[jj][5] = b.y; vals[jj][6] = b.z; vals[jj][7] = b.w;
        }
        #pragma unroll
        for (int h = 0; h < 8; h++) {
            uint2 o;
            o.x = packh(vals[0][h] * LOG2E, vals[1][h] * LOG2E);
            o.y = packh(vals[2][h] * LOG2E, vals[3][h] * LOG2E);
            *(uint2*)&g_bias[((size_t)h * Nn + i) * Nn + j] = o;
        }
    }
}

// ---------------------------------------------------------------------------
// Kernel 1: QKV GEMM (round-9/11 version): q/k 1-term, v 3-term fp16.
// ---------------------------------------------------------------------------
__global__ void __launch_bounds__(128) qkv_gemm_tc() {
    __shared__ __half Ah[2][64][40], Al[2][64][40];
    __shared__ __half Bh[2][64][40], Bl[2][64][40];

    const int m0 = blockIdx.x * 64;
    const int n0 = blockIdx.y * 64;
    const int tid = threadIdx.x;
    const int warp = tid >> 5, lane = tid & 31;
    const int g = lane >> 2, t = lane & 3;
    const int lsel = lane >> 3, lr = lane & 7;
    const int wy = warp >> 1, wx = warp & 1;
    const int tpart = n0 >> 8;
    const bool isv = (tpart == 2);

    auto issue = [&](int k0, int buf) {
        #pragma unroll
        for (int i = tid; i < 256; i += 128) {
            const int r = i >> 2, c = (i & 3) * 8;
            cpa16(&Ah[buf][r][c], &g_xh[(size_t)(m0 + r) * INP + k0 + c]);
            cpa16(&Bh[buf][r][c], &g_wqh[(size_t)(n0 + r) * INP + k0 + c]);
            if (isv) {
                cpa16(&Al[buf][r][c], &g_xl[(size_t)(m0 + r) * INP + k0 + c]);
                cpa16(&Bl[buf][r][c], &g_wql[(size_t)(n0 + r) * INP + k0 + c]);
            }
        }
        CP_COMMIT;
    };

    float c4[2][4][4] = {};
    issue(0, 0);

    for (int kk = 0; kk < 8; kk++) {
        const int buf = kk & 1;
        CP_WAIT0;
        __syncthreads();
        if (kk < 7) issue((kk + 1) * 32, buf ^ 1);

        #pragma unroll
        for (int kt = 0; kt < 2; kt++) {
            uint32_t ah[2][4], al[2][4];
            #pragma unroll
            for (int mi = 0; mi < 2; mi++) {
                const int r = wy * 32 + mi * 16 + (lsel & 1) * 8 + lr;
                const int cc = kt * 16 + (lsel >> 1) * 8;
                ldsm4(ah[mi][0], ah[mi][1], ah[mi][2], ah[mi][3], &Ah[buf][r][cc]);
                if (isv)
                    ldsm4(al[mi][0], al[mi][1], al[mi][2], al[mi][3], &Al[buf][r][cc]);
            }
            #pragma unroll
            for (int ntp = 0; ntp < 2; ntp++) {
                const int r = wx * 32 + ntp * 16 + (lsel >> 1) * 8 + lr;
                const int cc = kt * 16 + (lsel & 1) * 8;
                uint32_t b0, b1, b2, b3;
                ldsm4(b0, b1, b2, b3, &Bh[buf][r][cc]);
                if (isv) {
                    uint32_t e0, e1, e2, e3;
                    ldsm4(e0, e1, e2, e3, &Bl[buf][r][cc]);
                    #pragma unroll
                    for (int mi = 0; mi < 2; mi++) {
                        mma4(c4[mi][2*ntp],   ah[mi], b0, b1);
                        mma4(c4[mi][2*ntp],   ah[mi], e0, e1);
                        mma4(c4[mi][2*ntp],   al[mi], b0, b1);
                        mma4(c4[mi][2*ntp+1], ah[mi], b2, b3);
                        mma4(c4[mi][2*ntp+1], ah[mi], e2, e3);
                        mma4(c4[mi][2*ntp+1], al[mi], b2, b3);
                    }
                } else {
                    #pragma unroll
                    for (int mi = 0; mi < 2; mi++) {
                        mma4(c4[mi][2*ntp],   ah[mi], b0, b1);
                        mma4(c4[mi][2*ntp+1], ah[mi], b2, b3);
                    }
                }
            }
        }
    }

    const float qscale = 0.1767766952966369f * LOG2E;
    #pragma unroll
    for (int mi = 0; mi < 2; mi++) {
        #pragma unroll
        for (int ni = 0; ni < 4; ni++) {
            const int col = n0 + wx * 32 + ni * 8 + 2 * t;
            const int ci = col & 255;
            const int h = ci >> 5, d = ci & 31;
            #pragma unroll
            for (int half = 0; half < 2; half++) {
                const int r = m0 + wy * 32 + mi * 16 + g + half * 8;
                const int b = r >> 10, n = r & 1023;
                float v0 = c4[mi][ni][half * 2 + 0];
                float v1 = c4[mi][ni][half * 2 + 1];
                if (tpart == 0) {
                    v0 *= qscale; v1 *= qscale;
                    const size_t idx = (((size_t)(b * Hh + h)) * Nn + n) * Dd + d;
                    *(uint32_t*)&g_qh[idx] = packh(v0, v1);
                } else if (tpart == 1) {
                    const size_t idx = (((size_t)(b * Hh + h)) * Nn + n) * Dd + d;
                    *(uint32_t*)&g_kh[idx] = packh(v0, v1);
                } else {
                    uint32_t hi = packh(v0, v1);
                    float2 hf = unpackh(hi);
                    uint32_t lo = packh(v0 - hf.x, v1 - hf.y);
                    const size_t tv = (((size_t)(b * Hh + h)) * Dd + d) * Nn + n;
                    __half2 hb = *reinterpret_cast<__half2*>(&hi);
                    __half2 lb = *reinterpret_cast<__half2*>(&lo);
                    g_vth[tv] = hb.x;  g_vth[tv + Nn] = hb.y;
                    g_vtl[tv] = lb.x;  g_vtl[tv + Nn] = lb.y;
                }
            }
        }
    }
}

// ---------------------------------------------------------------------------
// Kernel 2: flash attention, fp16, TWO BATCHES per CTA (bias regs shared).
//   grid (16 qt, 8 h, 16 batch-pairs); 128 thr.
//   Per stage (28672 B): K0@0 [64][40] | K1@5120 | V0h@10240 [32][72] |
//                        V0l@14848 | V1h@19456 | V1l@24064.  2 stages = 57344.
// ---------------------------------------------------------------------------
#define ATTN_STAGE 28672
#define ATTN_SMEM  (2 * ATTN_STAGE)

__global__ void __launch_bounds__(128) attn_tc() {
    extern __shared__ __align__(16) char smr[];

    const int qt = blockIdx.x, h = blockIdx.y, bp = blockIdx.z;
    const int m0 = qt * 64;
    const int tid = threadIdx.x, warp = tid >> 5, lane = tid & 31;
    const int g = lane >> 2, t = lane & 3;
    const int lsel = lane >> 3, lr = lane & 7;

    const size_t head0 = (size_t)(2 * bp) * Hh + h;      // batch 2*bp
    const size_t kb[2] = { head0 * Nn * Dd, (head0 + Hh) * Nn * Dd };
    const size_t vb[2] = { head0 * Dd * Nn, (head0 + Hh) * Dd * Nn };
    const size_t bbase = ((size_t)h * Nn + (m0 + warp * 16)) * Nn;

    typedef __half (*row40)[40];
    typedef __half (*row72)[72];
    auto KT = [&](int buf, int bt) { return (row40)(smr + buf * ATTN_STAGE + bt * 5120); };
    auto VH = [&](int buf, int bt) { return (row72)(smr + buf * ATTN_STAGE + 10240 + bt * 9216); };
    auto VL = [&](int buf, int bt) { return (row72)(smr + buf * ATTN_STAGE + 14848 + bt * 9216); };
    // Q staging aliases buffer-1 K region (2 x 5120 = 10240 <= stage size)
    auto QS = [&](int bt) { return (row40)(smr + ATTN_STAGE + bt * 5120); };

    auto issue = [&](int j0, int buf) {
        // K: 2 batches x 256 16B-chunks
        #pragma unroll
        for (int i = tid; i < 512; i += 128) {
            const int bt = i >> 8, r = (i & 255) >> 2, c = (i & 3) * 8;
            cpa16(&KT(buf, bt)[r][c], &g_kh[kb[bt] + (size_t)(j0 + r) * Dd + c]);
        }
        // V hi/lo: 4 arrays x 256 chunks
        #pragma unroll
        for (int i = tid; i < 1024; i += 128) {
            const int w = i >> 8, r = (i & 255) >> 3, c = (i & 7) * 8;
            const int bt = w >> 1;
            __half* dst = (w & 1) ? &VL(buf, bt)[r][c] : &VH(buf, bt)[r][c];
            const __half* src = (w & 1) ? &g_vtl[vb[bt] + (size_t)r * Nn + j0 + c]
                                        : &g_vth[vb[bt] + (size_t)r * Nn + j0 + c];
            cpa16(dst, src);
        }
        CP_COMMIT;
    };

    issue(0, 0);

    {   // stage Q-hi for both batches into alias region (one row per thread)
        const int row = tid & 63, bq = tid >> 6;
        const uint4* sh = (const uint4*)&g_qh[(kb[bq] / 1) + 0];   // placeholder
        // real source: q rows of this batch
        const uint4* s = (const uint4*)&g_qh[((head0 + (size_t)bq * Hh) * Nn + m0 + row) * Dd];
        uint4* d = (uint4*)&QS(bq)[row][0];
        d[0] = s[0]; d[1] = s[1]; d[2] = s[2]; d[3] = s[3];
        (void)sh;
    }
    __syncthreads();

    uint32_t qfh[2][2][4];
    #pragma unroll
    for (int bt = 0; bt < 2; bt++)
        #pragma unroll
        for (int kt = 0; kt < 2; kt++) {
            const int r = warp * 16 + (lsel & 1) * 8 + lr;
            const int cc = kt * 16 + (lsel >> 1) * 8;
            ldsm4(qfh[bt][kt][0], qfh[bt][kt][1], qfh[bt][kt][2], qfh[bt][kt][3],
                  &QS(bt)[r][cc]);
        }

    float o[2][4][4] = {};
    float lacc[2][4] = {};

    for (int jt = 0; jt < 16; jt++) {
        const int buf = jt & 1;
        CP_WAIT0;
        __syncthreads();
        if (jt < 15) issue((jt + 1) * 64, buf ^ 1);

        // bias for this tile: shared by both batches (the whole point)
        const int j0 = jt * 64;
        uint32_t ub0[8], ub1[8];
        #pragma unroll
        for (int nt = 0; nt < 8; nt++) {
            const int j = j0 + nt * 8 + 2 * t;
            ub0[nt] = *(const uint32_t*)&g_bias[bbase + (size_t)g * Nn + j];
            ub1[nt] = *(const uint32_t*)&g_bias[bbase + (size_t)(g + 8) * Nn + j];
        }

        #pragma unroll
        for (int bt = 0; bt < 2; bt++) {
            row40 kh = KT(buf, bt);
            row72 vh = VH(buf, bt); row72 vl = VL(buf, bt);

            float sc[8][4];
            #pragma unroll
            for (int nt = 0; nt < 8; nt++)
                sc[nt][0] = sc[nt][1] = sc[nt][2] = sc[nt][3] = 0.f;

            // S = Qh * Kh (1-term fp16)
            #pragma unroll
            for (int kt = 0; kt < 2; kt++) {
                const int cc = kt * 16 + (lsel & 1) * 8;
                #pragma unroll
                for (int ntp = 0; ntp < 4; ntp++) {
                    const int r = ntp * 16 + (lsel >> 1) * 8 + lr;
                    uint32_t h0, h1, h2, h3;
                    ldsm4(h0, h1, h2, h3, &kh[r][cc]);
                    mma4(sc[2*ntp],   qfh[bt][kt], h0, h1);
                    mma4(sc[2*ntp+1], qfh[bt][kt], h2, h3);
                }
            }

            // softmax f16x2: P = ex2(pack(S) + bias)
            uint32_t pp[8][2];
            #pragma unroll
            for (int nt = 0; nt < 8; nt++) {
                pp[nt][0] = ex2h2(hadd2u(packh(sc[nt][0], sc[nt][1]), ub0[nt]));
                pp[nt][1] = ex2h2(hadd2u(packh(sc[nt][2], sc[nt][3]), ub1[nt]));
            }

            // O += P V (2-term) + row-sum via ones-column MMA
            #pragma unroll
            for (int kt2 = 0; kt2 < 4; kt2++) {
                uint32_t pah[4];
                pah[0] = pp[2*kt2][0];
                pah[1] = pp[2*kt2][1];
                pah[2] = pp[2*kt2+1][0];
                pah[3] = pp[2*kt2+1][1];

                const int cc = kt2 * 16 + (lsel & 1) * 8;
                const int rA = (lsel >> 1) * 8 + lr;
                uint32_t v0, v1, v2, v3, w0, w1, w2, w3;
                ldsm4(v0, v1, v2, v3, &vh[rA][cc]);
                ldsm4(w0, w1, w2, w3, &vl[rA][cc]);
                mma4(o[bt][0], pah, v0, v1); mma4(o[bt][0], pah, w0, w1);
                mma4(o[bt][1], pah, v2, v3); mma4(o[bt][1], pah, w2, w3);
                ldsm4(v0, v1, v2, v3, &vh[16 + rA][cc]);
                ldsm4(w0, w1, w2, w3, &vl[16 + rA][cc]);
                mma4(o[bt][2], pah, v0, v1); mma4(o[bt][2], pah, w0, w1);
                mma4(o[bt][3], pah, v2, v3); mma4(o[bt][3], pah, w2, w3);
                mma4(lacc[bt], pah, ONES_H2, ONES_H2);
            }
        }
    }

    #pragma unroll
    for (int bt = 0; bt < 2; bt++) {
        const float inv0 = 1.f / lacc[bt][0], inv1 = 1.f / lacc[bt][2];
        const int bglob = 2 * bp + bt;
        #pragma unroll
        for (int nv = 0; nv < 4; nv++) {
            const int colb = h * 32 + nv * 8 + 2 * t;
            const int r0 = m0 + warp * 16 + g;
            const size_t i0 = ((size_t)bglob * Nn + r0) * INNER + colb;
            const size_t i1 = i0 + (size_t)8 * INNER;
            *(uint32_t*)&g_oh[i0] = packh(o[bt][nv][0] * inv0, o[bt][nv][1] * inv0);
            *(uint32_t*)&g_oh[i1] = packh(o[bt][nv][2] * inv1, o[bt][nv][3] * inv1);
        }
    }
}

// ---------------------------------------------------------------------------
// Kernel 3: out-projection GEMM, 2-term: Out = Oh*(Wh + Wl) + b
// ---------------------------------------------------------------------------
__global__ void __launch_bounds__(128) out_gemm_tc(
    const float* __restrict__ bias, float* __restrict__ out)
{
    __shared__ __half Ah[2][64][40];
    __shared__ __half Bh[2][64][40], Bl[2][64][40];

    const int m0 = blockIdx.x * 64;
    const int n0 = blockIdx.y * 64;
    const int tid = threadIdx.x;
    const int warp = tid >> 5, lane = tid & 31;
    const int g = lane >> 2, t = lane & 3;
    const int lsel = lane >> 3, lr = lane & 7;
    const int wy = warp >> 1, wx = warp & 1;

    auto issue = [&](int k0, int buf) {
        #pragma unroll
        for (int i = tid; i < 256; i += 128) {
            const int r = i >> 2, c = (i & 3) * 8;
            cpa16(&Ah[buf][r][c], &g_oh[(size_t)(m0 + r) * INNER + k0 + c]);
            cpa16(&Bh[buf][r][c], &g_woh[(size_t)(n0 + r) * INNER + k0 + c]);
            cpa16(&Bl[buf][r][c], &g_wol[(size_t)(n0 + r) * INNER + k0 + c]);
        }
        CP_COMMIT;
    };

    float c4[2][4][4] = {};
    issue(0, 0);

    for (int kk = 0; kk < 8; kk++) {
        const int buf = kk & 1;
        CP_WAIT0;
        __syncthreads();
        if (kk < 7) issue((kk + 1) * 32, buf ^ 1);

        #pragma unroll
        for (int kt = 0; kt < 2; kt++) {
            uint32_t ah[2][4];
            #pragma unroll
            for (int mi = 0; mi < 2; mi++) {
                const int r = wy * 32 + mi * 16 + (lsel & 1) * 8 + lr;
                const int cc = kt * 16 + (lsel >> 1) * 8;
                ldsm4(ah[mi][0], ah[mi][1], ah[mi][2], ah[mi][3], &Ah[buf][r][cc]);
            }
            #pragma unroll
            for (int ntp = 0; ntp < 2; ntp++) {
                const int r = wx * 32 + ntp * 16 + (lsel >> 1) * 8 + lr;
                const int cc = kt * 16 + (lsel & 1) * 8;
                uint32_t b0, b1, b2, b3, e0, e1, e2, e3;
                ldsm4(b0, b1, b2, b3, &Bh[buf][r][cc]);
                ldsm4(e0, e1, e2, e3, &Bl[buf][r][cc]);
                #pragma unroll
                for (int mi = 0; mi < 2; mi++) {
                    mma4(c4[mi][2*ntp],   ah[mi], b0, b1);
                    mma4(c4[mi][2*ntp],   ah[mi], e0, e1);
                    mma4(c4[mi][2*ntp+1], ah[mi], b2, b3);
                    mma4(c4[mi][2*ntp+1], ah[mi], e2, e3);
                }
            }
        }
    }

    #pragma unroll
    for (int mi = 0; mi < 2; mi++) {
        #pragma unroll
        for (int ni = 0; ni < 4; ni++) {
            const int col = n0 + wx * 32 + ni * 8 + 2 * t;
            const float b0 = bias[col], b1 = bias[col + 1];
            #pragma unroll
            for (int half = 0; half < 2; half++) {
                const int r = m0 + wy * 32 + mi * 16 + g + half * 8;
                float2 v = make_float2(c4[mi][ni][half * 2 + 0] + b0,
                                       c4[mi][ni][half * 2 + 1] + b1);
                *(float2*)&out[(size_t)r * OUP + col] = v;
            }
        }
    }
}

// ---------------------------------------------------------------------------
// Launch
// ---------------------------------------------------------------------------
extern "C" void kernel_launch(void* const* d_in, const int* in_sizes, int n_in,
                              void* d_out, int out_size)
{
    const float* x          = (const float*)d_in[0];
    const float* W_qkv      = (const float*)d_in[1];
    const float* bias_table = (const float*)d_in[2];
    const float* W_out      = (const float*)d_in[3];
    const float* b_out      = (const float*)d_in[4];
    const int*   rel_index  = (const int*)d_in[5];
    float* out = (float*)d_out;
    (void)in_sizes; (void)n_in; (void)out_size;

    cudaFuncSetAttribute(attn_tc, cudaFuncAttributeMaxDynamicSharedMemorySize, ATTN_SMEM);

    prep_all<<<10240, 256>>>(x, W_qkv, W_out, bias_table, rel_index);

    qkv_gemm_tc<<<dim3(NTOK / 64, QKVC / 64), 128>>>();            // (512, 12)
    attn_tc<<<dim3(Nn / 64, Hh, Bc / 2), 128, ATTN_SMEM>>>();      // (16, 8, 16)
    out_gemm_tc<<<dim3(NTOK / 64, OUP / 64), 128>>>(b_out, out);   // (512, 4)
}

// round 16
// speedup vs baseline: 1.3211x; 1.3211x over previous
#include <cuda_runtime.h>
#include <cuda_fp16.h>
#include <cstdint>

#define Bc 32
#define Nn 1024
#define INP 256
#define Hh 8
#define Dd 32
#define INNER 256
#define OUP 256
#define QKVC 768
#define NTOK (Bc * Nn)

#define LOG2E 1.4426950408889634f
#define ONES_H2 0x3C003C00u     // half2(1.0, 1.0)

// ---------------------------------------------------------------------------
// Device-global scratch (fp16 hi/lo)
// ---------------------------------------------------------------------------
__device__ __half g_xh[NTOK * INP],  g_xl[NTOK * INP];
__device__ __half g_wqh[QKVC * INP], g_wql[QKVC * INP];      // W_qkv^T [n][k]
__device__ __half g_woh[OUP * INNER], g_wol[OUP * INNER];    // W_out^T [n][k]
__device__ __half g_qh[Bc*Hh*Nn*Dd];                         // [b,h,n,d] *scale*log2e
__device__ __half g_kh[Bc*Hh*Nn*Dd];                         // hi only (S is 1-term)
__device__ __half g_vth[Bc*Hh*Dd*Nn], g_vtl[Bc*Hh*Dd*Nn];    // [b,h,d,n]
__device__ __half g_oh[NTOK * INNER];                        // attn out, hi only
__device__ __half g_bias[Hh * Nn * Nn];                      // [h][i][j] * log2e

// ---------------------------------------------------------------------------
// Helpers
// ---------------------------------------------------------------------------
__device__ __forceinline__ uint32_t packh(float x, float y) {
    __half2 t = __floats2half2_rn(x, y);
    return *reinterpret_cast<uint32_t*>(&t);
}
__device__ __forceinline__ float2 unpackh(uint32_t u) {
    __half2 t = *reinterpret_cast<__half2*>(&u);
    return __half22float2(t);
}
__device__ __forceinline__ uint32_t hadd2u(uint32_t a, uint32_t b) {
    uint32_t d;
    asm("add.f16x2 %0, %1, %2;" : "=r"(d) : "r"(a), "r"(b));
    return d;
}
__device__ __forceinline__ uint32_t ex2h2(uint32_t a) {
    uint32_t d;
    asm("ex2.approx.f16x2 %0, %1;" : "=r"(d) : "r"(a));
    return d;
}
__device__ __forceinline__ void mma4(float* c, const uint32_t* a, uint32_t b0, uint32_t b1) {
    asm volatile(
        "mma.sync.aligned.m16n8k16.row.col.f32.f16.f16.f32 "
        "{%0,%1,%2,%3}, {%4,%5,%6,%7}, {%8,%9}, {%0,%1,%2,%3};\n"
        : "+f"(c[0]), "+f"(c[1]), "+f"(c[2]), "+f"(c[3])
        : "r"(a[0]), "r"(a[1]), "r"(a[2]), "r"(a[3]), "r"(b0), "r"(b1));
}
__device__ __forceinline__ void ldsm4(uint32_t& r0, uint32_t& r1, uint32_t& r2,
                                      uint32_t& r3, const void* p) {
    uint32_t a = (uint32_t)__cvta_generic_to_shared(p);
    asm volatile("ldmatrix.sync.aligned.m8n8.x4.shared.b16 {%0,%1,%2,%3}, [%4];"
                 : "=r"(r0), "=r"(r1), "=r"(r2), "=r"(r3) : "r"(a));
}
__device__ __forceinline__ void cpa16(void* dst, const void* src) {
    uint32_t d = (uint32_t)__cvta_generic_to_shared(dst);
    asm volatile("cp.async.cg.shared.global [%0], [%1], 16;" :: "r"(d), "l"(src));
}
#define CP_COMMIT asm volatile("cp.async.commit_group;")
#define CP_WAIT0  asm volatile("cp.async.wait_group 0;")

// ---------------------------------------------------------------------------
// Merged prep kernel (one launch):
//   blocks [0, 8192)      : x split
//   blocks [8192, 8960)   : W_qkv^T split
//   blocks [8960, 9216)   : W_out^T split
//   blocks [9216, 10240)  : bias gather * log2e
// ---------------------------------------------------------------------------
__global__ void __launch_bounds__(256) prep_all(
    const float* __restrict__ x, const float* __restrict__ wq,
    const float* __restrict__ wo, const float* __restrict__ table,
    const int* __restrict__ rel_index)
{
    const int bid = blockIdx.x;
    if (bid < 8192) {
        size_t i = (size_t)bid * 256 + threadIdx.x;
        float4 v = ((const float4*)x)[i];
        uint32_t h01 = packh(v.x, v.y), h23 = packh(v.z, v.w);
        float2 a = unpackh(h01), b = unpackh(h23);
        ((uint2*)g_xh)[i] = make_uint2(h01, h23);
        ((uint2*)g_xl)[i] = make_uint2(packh(v.x - a.x, v.y - a.y),
                                       packh(v.z - b.x, v.w - b.y));
    } else if (bid < 8960) {
        int i = (bid - 8192) * 256 + threadIdx.x;
        int k = i / QKVC, n = i % QKVC;
        float v = wq[i];
        __half h = __float2half_rn(v);
        g_wqh[n * INP + k] = h;
        g_wql[n * INP + k] = __float2half_rn(v - __half2float(h));
    } else if (bid < 9216) {
        int i = (bid - 8960) * 256 + threadIdx.x;
        int k = i >> 8, n = i & 255;
        float v = wo[i];
        __half h = __float2half_rn(v);
        g_woh[n * INNER + k] = h;
        g_wol[n * INNER + k] = __float2half_rn(v - __half2float(h));
    } else {
        int tI = (bid - 9216) * 256 + threadIdx.x;
        int i = tI >> 8;
        int j = (tI & 255) * 4;
        int4 idx = *(const int4*)&rel_index[i * Nn + j];
        int id[4] = {idx.x, idx.y, idx.z, idx.w};
        float vals[4][8];
        #pragma unroll
        for (int jj = 0; jj < 4; jj++) {
            const float4* tp = (const float4*)(table + (size_t)id[jj] * 8);
            float4 a = tp[0], b = tp[1];
            vals[jj][0] = a.x; vals[jj][1] = a.y; vals[jj][2] = a.z; vals[jj][3] = a.w;
            vals[jj][4] = b.x; vals[jj][5] = b.y; vals[jj][6] = b.z; vals[jj][7] = b.w;
        }
        #pragma unroll
        for (int h = 0; h < 8; h++) {
            uint2 o;
            o.x = packh(vals[0][h] * LOG2E, vals[1][h] * LOG2E);
            o.y = packh(vals[2][h] * LOG2E, vals[3][h] * LOG2E);
            *(uint2*)&g_bias[((size_t)h * Nn + i) * Nn + j] = o;
        }
    }
}

// ---------------------------------------------------------------------------
// Kernel 1: QKV GEMM (round-11 proven): q/k 1-term, v 3-term fp16.
// ---------------------------------------------------------------------------
__global__ void __launch_bounds__(128) qkv_gemm_tc() {
    __shared__ __half Ah[2][64][40], Al[2][64][40];
    __shared__ __half Bh[2][64][40], Bl[2][64][40];

    const int m0 = blockIdx.x * 64;
    const int n0 = blockIdx.y * 64;
    const int tid = threadIdx.x;
    const int warp = tid >> 5, lane = tid & 31;
    const int g = lane >> 2, t = lane & 3;
    const int lsel = lane >> 3, lr = lane & 7;
    const int wy = warp >> 1, wx = warp & 1;
    const int tpart = n0 >> 8;
    const bool isv = (tpart == 2);

    auto issue = [&](int k0, int buf) {
        #pragma unroll
        for (int i = tid; i < 256; i += 128) {
            const int r = i >> 2, c = (i & 3) * 8;
            cpa16(&Ah[buf][r][c], &g_xh[(size_t)(m0 + r) * INP + k0 + c]);
            cpa16(&Bh[buf][r][c], &g_wqh[(size_t)(n0 + r) * INP + k0 + c]);
            if (isv) {
                cpa16(&Al[buf][r][c], &g_xl[(size_t)(m0 + r) * INP + k0 + c]);
                cpa16(&Bl[buf][r][c], &g_wql[(size_t)(n0 + r) * INP + k0 + c]);
            }
        }
        CP_COMMIT;
    };

    float c4[2][4][4] = {};
    issue(0, 0);

    for (int kk = 0; kk < 8; kk++) {
        const int buf = kk & 1;
        CP_WAIT0;
        __syncthreads();
        if (kk < 7) issue((kk + 1) * 32, buf ^ 1);

        #pragma unroll
        for (int kt = 0; kt < 2; kt++) {
            uint32_t ah[2][4], al[2][4];
            #pragma unroll
            for (int mi = 0; mi < 2; mi++) {
                const int r = wy * 32 + mi * 16 + (lsel & 1) * 8 + lr;
                const int cc = kt * 16 + (lsel >> 1) * 8;
                ldsm4(ah[mi][0], ah[mi][1], ah[mi][2], ah[mi][3], &Ah[buf][r][cc]);
                if (isv)
                    ldsm4(al[mi][0], al[mi][1], al[mi][2], al[mi][3], &Al[buf][r][cc]);
            }
            #pragma unroll
            for (int ntp = 0; ntp < 2; ntp++) {
                const int r = wx * 32 + ntp * 16 + (lsel >> 1) * 8 + lr;
                const int cc = kt * 16 + (lsel & 1) * 8;
                uint32_t b0, b1, b2, b3;
                ldsm4(b0, b1, b2, b3, &Bh[buf][r][cc]);
                if (isv) {
                    uint32_t e0, e1, e2, e3;
                    ldsm4(e0, e1, e2, e3, &Bl[buf][r][cc]);
                    #pragma unroll
                    for (int mi = 0; mi < 2; mi++) {
                        mma4(c4[mi][2*ntp],   ah[mi], b0, b1);
                        mma4(c4[mi][2*ntp],   ah[mi], e0, e1);
                        mma4(c4[mi][2*ntp],   al[mi], b0, b1);
                        mma4(c4[mi][2*ntp+1], ah[mi], b2, b3);
                        mma4(c4[mi][2*ntp+1], ah[mi], e2, e3);
                        mma4(c4[mi][2*ntp+1], al[mi], b2, b3);
                    }
                } else {
                    #pragma unroll
                    for (int mi = 0; mi < 2; mi++) {
                        mma4(c4[mi][2*ntp],   ah[mi], b0, b1);
                        mma4(c4[mi][2*ntp+1], ah[mi], b2, b3);
                    }
                }
            }
        }
    }

    const float qscale = 0.1767766952966369f * LOG2E;
    #pragma unroll
    for (int mi = 0; mi < 2; mi++) {
        #pragma unroll
        for (int ni = 0; ni < 4; ni++) {
            const int col = n0 + wx * 32 + ni * 8 + 2 * t;
            const int ci = col & 255;
            const int h = ci >> 5, d = ci & 31;
            #pragma unroll
            for (int half = 0; half < 2; half++) {
                const int r = m0 + wy * 32 + mi * 16 + g + half * 8;
                const int b = r >> 10, n = r & 1023;
                float v0 = c4[mi][ni][half * 2 + 0];
                float v1 = c4[mi][ni][half * 2 + 1];
                if (tpart == 0) {
                    v0 *= qscale; v1 *= qscale;
                    const size_t idx = (((size_t)(b * Hh + h)) * Nn + n) * Dd + d;
                    *(uint32_t*)&g_qh[idx] = packh(v0, v1);
                } else if (tpart == 1) {
                    const size_t idx = (((size_t)(b * Hh + h)) * Nn + n) * Dd + d;
                    *(uint32_t*)&g_kh[idx] = packh(v0, v1);
                } else {
                    uint32_t hi = packh(v0, v1);
                    float2 hf = unpackh(hi);
                    uint32_t lo = packh(v0 - hf.x, v1 - hf.y);
                    const size_t tv = (((size_t)(b * Hh + h)) * Dd + d) * Nn + n;
                    __half2 hb = *reinterpret_cast<__half2*>(&hi);
                    __half2 lb = *reinterpret_cast<__half2*>(&lo);
                    g_vth[tv] = hb.x;  g_vth[tv + Nn] = hb.y;
                    g_vtl[tv] = lb.x;  g_vtl[tv + Nn] = lb.y;
                }
            }
        }
    }
}

// ---------------------------------------------------------------------------
// Kernel 2: flash attention (round-11 proven, 401us config):
//   S = Qh*Kh (1-term); P = ex2.f16x2(pack(S) + bias_h2); PV 2-term;
//   row sums via ones-column MMA. 64 q-rows/CTA, 4 warps, dbuf cp.async.
//   per-buf: Kh@0 [64][40] | Vh@5120 [32][72] | Vl@9728; stride 14336
// ---------------------------------------------------------------------------
__global__ void __launch_bounds__(128) attn_tc() {
    __shared__ __align__(16) char smr[2 * 14336];

    const int qt = blockIdx.x, h = blockIdx.y, b = blockIdx.z;
    const int m0 = qt * 64;
    const int tid = threadIdx.x, warp = tid >> 5, lane = tid & 31;
    const int g = lane >> 2, t = lane & 3;
    const int lsel = lane >> 3, lr = lane & 7;

    const size_t head = (size_t)(b * Hh + h);
    const size_t qoff = (head * Nn + m0) * Dd;
    const size_t kbase = head * Nn * Dd;
    const size_t vbase = head * Dd * Nn;
    const size_t bbase = ((size_t)h * Nn + (m0 + warp * 16)) * Nn;

    typedef __half (*row40)[40];
    typedef __half (*row72)[72];
    auto KH = [&](int buf) { return (row40)(smr + buf * 14336); };
    auto VH = [&](int buf) { return (row72)(smr + buf * 14336 + 5120); };
    auto VL = [&](int buf) { return (row72)(smr + buf * 14336 + 9728); };
    row40 Qh = (row40)(smr + 14336);   // Q staging aliases buf1 Kh

    auto issue = [&](int j0, int buf) {
        row40 kh = KH(buf);
        row72 vh = VH(buf); row72 vl = VL(buf);
        #pragma unroll
        for (int i = tid; i < 256; i += 128) {
            const int r = i >> 2, c = (i & 3) * 8;
            cpa16(&kh[r][c], &g_kh[kbase + (size_t)(j0 + r) * Dd + c]);
        }
        #pragma unroll
        for (int i = tid; i < 256; i += 128) {
            const int r = i >> 3, c = (i & 7) * 8;
            cpa16(&vh[r][c], &g_vth[vbase + (size_t)r * Nn + j0 + c]);
            cpa16(&vl[r][c], &g_vtl[vbase + (size_t)r * Nn + j0 + c]);
        }
        CP_COMMIT;
    };

    issue(0, 0);

    {   // stage Q-hi into alias region
        const int row = tid & 63;
        const int u = (tid >> 6) * 2;
        const uint4* sh = (const uint4*)&g_qh[qoff + (size_t)row * Dd];
        ((uint4*)&Qh[row][0])[u]     = sh[u];
        ((uint4*)&Qh[row][0])[u + 1] = sh[u + 1];
    }
    __syncthreads();

    uint32_t qfh[2][4];
    #pragma unroll
    for (int kt = 0; kt < 2; kt++) {
        const int r = warp * 16 + (lsel & 1) * 8 + lr;
        const int cc = kt * 16 + (lsel >> 1) * 8;
        ldsm4(qfh[kt][0], qfh[kt][1], qfh[kt][2], qfh[kt][3], &Qh[r][cc]);
    }

    float o[4][4] = {};
    float lacc[4] = {};   // ones-column MMA accumulator: [0]=row g, [2]=row g+8

    for (int jt = 0; jt < 16; jt++) {
        const int buf = jt & 1;
        CP_WAIT0;
        __syncthreads();
        if (jt < 15) issue((jt + 1) * 64, buf ^ 1);

        row40 kh = KH(buf);
        row72 vh = VH(buf); row72 vl = VL(buf);

        float sc[8][4];
        #pragma unroll
        for (int nt = 0; nt < 8; nt++)
            sc[nt][0] = sc[nt][1] = sc[nt][2] = sc[nt][3] = 0.f;

        // S = Qh * Kh (1-term fp16)
        #pragma unroll
        for (int kt = 0; kt < 2; kt++) {
            const int cc = kt * 16 + (lsel & 1) * 8;
            #pragma unroll
            for (int ntp = 0; ntp < 4; ntp++) {
                const int r = ntp * 16 + (lsel >> 1) * 8 + lr;
                uint32_t h0, h1, h2, h3;
                ldsm4(h0, h1, h2, h3, &kh[r][cc]);
                mma4(sc[2*ntp],   qfh[kt], h0, h1);
                mma4(sc[2*ntp+1], qfh[kt], h2, h3);
            }
        }

        // softmax, f16x2: pack(S) + bias_h2 -> ex2.f16x2 -> P
        const int j0 = jt * 64;
        uint32_t pp[8][2];
        #pragma unroll
        for (int nt = 0; nt < 8; nt++) {
            const int j = j0 + nt * 8 + 2 * t;
            uint32_t u0 = *(const uint32_t*)&g_bias[bbase + (size_t)g * Nn + j];
            uint32_t u1 = *(const uint32_t*)&g_bias[bbase + (size_t)(g + 8) * Nn + j];
            pp[nt][0] = ex2h2(hadd2u(packh(sc[nt][0], sc[nt][1]), u0));
            pp[nt][1] = ex2h2(hadd2u(packh(sc[nt][2], sc[nt][3]), u1));
        }

        // O += P V (2-term) + row-sum via ones-column MMA
        #pragma unroll
        for (int kt2 = 0; kt2 < 4; kt2++) {
            uint32_t pah[4];
            pah[0] = pp[2*kt2][0];
            pah[1] = pp[2*kt2][1];
            pah[2] = pp[2*kt2+1][0];
            pah[3] = pp[2*kt2+1][1];

            const int cc = kt2 * 16 + (lsel & 1) * 8;
            const int rA = (lsel >> 1) * 8 + lr;
            uint32_t v0, v1, v2, v3, w0, w1, w2, w3;
            ldsm4(v0, v1, v2, v3, &vh[rA][cc]);
            ldsm4(w0, w1, w2, w3, &vl[rA][cc]);
            mma4(o[0], pah, v0, v1); mma4(o[0], pah, w0, w1);
            mma4(o[1], pah, v2, v3); mma4(o[1], pah, w2, w3);
            ldsm4(v0, v1, v2, v3, &vh[16 + rA][cc]);
            ldsm4(w0, w1, w2, w3, &vl[16 + rA][cc]);
            mma4(o[2], pah, v0, v1); mma4(o[2], pah, w0, w1);
            mma4(o[3], pah, v2, v3); mma4(o[3], pah, w2, w3);
            mma4(lacc, pah, ONES_H2, ONES_H2);   // row sums
        }
    }

    const float inv0 = 1.f / lacc[0], inv1 = 1.f / lacc[2];

    #pragma unroll
    for (int nv = 0; nv < 4; nv++) {
        const int colb = h * 32 + nv * 8 + 2 * t;
        const int r0 = m0 + warp * 16 + g;
        const size_t i0 = ((size_t)b * Nn + r0) * INNER + colb;
        const size_t i1 = i0 + (size_t)8 * INNER;
        *(uint32_t*)&g_oh[i0] = packh(o[nv][0] * inv0, o[nv][1] * inv0);
        *(uint32_t*)&g_oh[i1] = packh(o[nv][2] * inv1, o[nv][3] * inv1);
    }
}

// ---------------------------------------------------------------------------
// Kernel 3: out-projection GEMM (round-11 proven), 2-term: Oh*(Wh + Wl) + b
// ---------------------------------------------------------------------------
__global__ void __launch_bounds__(128) out_gemm_tc(
    const float* __restrict__ bias, float* __restrict__ out)
{
    __shared__ __half Ah[2][64][40];
    __shared__ __half Bh[2][64][40], Bl[2][64][40];

    const int m0 = blockIdx.x * 64;
    const int n0 = blockIdx.y * 64;
    const int tid = threadIdx.x;
    const int warp = tid >> 5, lane = tid & 31;
    const int g = lane >> 2, t = lane & 3;
    const int lsel = lane >> 3, lr = lane & 7;
    const int wy = warp >> 1, wx = warp & 1;

    auto issue = [&](int k0, int buf) {
        #pragma unroll
        for (int i = tid; i < 256; i += 128) {
            const int r = i >> 2, c = (i & 3) * 8;
            cpa16(&Ah[buf][r][c], &g_oh[(size_t)(m0 + r) * INNER + k0 + c]);
            cpa16(&Bh[buf][r][c], &g_woh[(size_t)(n0 + r) * INNER + k0 + c]);
            cpa16(&Bl[buf][r][c], &g_wol[(size_t)(n0 + r) * INNER + k0 + c]);
        }
        CP_COMMIT;
    };

    float c4[2][4][4] = {};
    issue(0, 0);

    for (int kk = 0; kk < 8; kk++) {
        const int buf = kk & 1;
        CP_WAIT0;
        __syncthreads();
        if (kk < 7) issue((kk + 1) * 32, buf ^ 1);

        #pragma unroll
        for (int kt = 0; kt < 2; kt++) {
            uint32_t ah[2][4];
            #pragma unroll
            for (int mi = 0; mi < 2; mi++) {
                const int r = wy * 32 + mi * 16 + (lsel & 1) * 8 + lr;
                const int cc = kt * 16 + (lsel >> 1) * 8;
                ldsm4(ah[mi][0], ah[mi][1], ah[mi][2], ah[mi][3], &Ah[buf][r][cc]);
            }
            #pragma unroll
            for (int ntp = 0; ntp < 2; ntp++) {
                const int r = wx * 32 + ntp * 16 + (lsel >> 1) * 8 + lr;
                const int cc = kt * 16 + (lsel & 1) * 8;
                uint32_t b0, b1, b2, b3, e0, e1, e2, e3;
                ldsm4(b0, b1, b2, b3, &Bh[buf][r][cc]);
                ldsm4(e0, e1, e2, e3, &Bl[buf][r][cc]);
                #pragma unroll
                for (int mi = 0; mi < 2; mi++) {
                    mma4(c4[mi][2*ntp],   ah[mi], b0, b1);
                    mma4(c4[mi][2*ntp],   ah[mi], e0, e1);
                    mma4(c4[mi][2*ntp+1], ah[mi], b2, b3);
                    mma4(c4[mi][2*ntp+1], ah[mi], e2, e3);
                }
            }
        }
    }

    #pragma unroll
    for (int mi = 0; mi < 2; mi++) {
        #pragma unroll
        for (int ni = 0; ni < 4; ni++) {
            const int col = n0 + wx * 32 + ni * 8 + 2 * t;
            const float b0 = bias[col], b1 = bias[col + 1];
            #pragma unroll
            for (int half = 0; half < 2; half++) {
                const int r = m0 + wy * 32 + mi * 16 + g + half * 8;
                float2 v = make_float2(c4[mi][ni][half * 2 + 0] + b0,
                                       c4[mi][ni][half * 2 + 1] + b1);
                *(float2*)&out[(size_t)r * OUP + col] = v;
            }
        }
    }
}

// ---------------------------------------------------------------------------
// Launch
// ---------------------------------------------------------------------------
extern "C" void kernel_launch(void* const* d_in, const int* in_sizes, int n_in,
                              void* d_out, int out_size)
{
    const float* x          = (const float*)d_in[0];
    const float* W_qkv      = (const float*)d_in[1];
    const float* bias_table = (const float*)d_in[2];
    const float* W_out      = (const float*)d_in[3];
    const float* b_out      = (const float*)d_in[4];
    const int*   rel_index  = (const int*)d_in[5];
    float* out = (float*)d_out;
    (void)in_sizes; (void)n_in; (void)out_size;

    prep_all<<<10240, 256>>>(x, W_qkv, W_out, bias_table, rel_index);

    qkv_gemm_tc<<<dim3(NTOK / 64, QKVC / 64), 128>>>();          // (512, 12)
    attn_tc<<<dim3(Nn / 64, Hh, Bc), 128>>>();                   // (16, 8, 32)
    out_gemm_tc<<<dim3(NTOK / 64, OUP / 64), 128>>>(b_out, out); // (512, 4)
}

// round 17
// speedup vs baseline: 1.3219x; 1.0007x over previous
#include <cuda_runtime.h>
#include <cuda_fp16.h>
#include <cstdint>

#define Bc 32
#define Nn 1024
#define INP 256
#define Hh 8
#define Dd 32
#define INNER 256
#define OUP 256
#define QKVC 768
#define NTOK (Bc * Nn)

#define LOG2E 1.4426950408889634f
#define ONES_H2 0x3C003C00u     // half2(1.0, 1.0)

// ---------------------------------------------------------------------------
// Device-global scratch (fp16 hi/lo)
// ---------------------------------------------------------------------------
__device__ __half g_xh[NTOK * INP],  g_xl[NTOK * INP];
__device__ __half g_wqh[QKVC * INP], g_wql[QKVC * INP];      // W_qkv^T [n][k]
__device__ __half g_woh[OUP * INNER], g_wol[OUP * INNER];    // W_out^T [n][k]
__device__ __half g_qh[Bc*Hh*Nn*Dd];                         // [b,h,n,d] *scale*log2e
__device__ __half g_kh[Bc*Hh*Nn*Dd];                         // hi only (S is 1-term)
__device__ __half g_vth[Bc*Hh*Dd*Nn], g_vtl[Bc*Hh*Dd*Nn];    // [b,h,d,n]
__device__ __half g_oh[NTOK * INNER];                        // attn out, hi only
__device__ __half g_bias[Hh * Nn * Nn];                      // [h][i][j] * log2e

// ---------------------------------------------------------------------------
// Helpers
// ---------------------------------------------------------------------------
__device__ __forceinline__ uint32_t packh(float x, float y) {
    __half2 t = __floats2half2_rn(x, y);
    return *reinterpret_cast<uint32_t*>(&t);
}
__device__ __forceinline__ float2 unpackh(uint32_t u) {
    __half2 t = *reinterpret_cast<__half2*>(&u);
    return __half22float2(t);
}
__device__ __forceinline__ uint32_t hadd2u(uint32_t a, uint32_t b) {
    uint32_t d;
    asm("add.f16x2 %0, %1, %2;" : "=r"(d) : "r"(a), "r"(b));
    return d;
}
__device__ __forceinline__ uint32_t ex2h2(uint32_t a) {
    uint32_t d;
    asm("ex2.approx.f16x2 %0, %1;" : "=r"(d) : "r"(a));
    return d;
}
__device__ __forceinline__ void mma4(float* c, const uint32_t* a, uint32_t b0, uint32_t b1) {
    asm volatile(
        "mma.sync.aligned.m16n8k16.row.col.f32.f16.f16.f32 "
        "{%0,%1,%2,%3}, {%4,%5,%6,%7}, {%8,%9}, {%0,%1,%2,%3};\n"
        : "+f"(c[0]), "+f"(c[1]), "+f"(c[2]), "+f"(c[3])
        : "r"(a[0]), "r"(a[1]), "r"(a[2]), "r"(a[3]), "r"(b0), "r"(b1));
}
__device__ __forceinline__ void ldsm4(uint32_t& r0, uint32_t& r1, uint32_t& r2,
                                      uint32_t& r3, const void* p) {
    uint32_t a = (uint32_t)__cvta_generic_to_shared(p);
    asm volatile("ldmatrix.sync.aligned.m8n8.x4.shared.b16 {%0,%1,%2,%3}, [%4];"
                 : "=r"(r0), "=r"(r1), "=r"(r2), "=r"(r3) : "r"(a));
}
__device__ __forceinline__ void cpa16(void* dst, const void* src) {
    uint32_t d = (uint32_t)__cvta_generic_to_shared(dst);
    asm volatile("cp.async.cg.shared.global [%0], [%1], 16;" :: "r"(d), "l"(src));
}
#define CP_COMMIT asm volatile("cp.async.commit_group;")
#define CP_WAIT0  asm volatile("cp.async.wait_group 0;")

// ---------------------------------------------------------------------------
// Merged prep kernel (one launch):
//   blocks [0, 8192)      : x split
//   blocks [8192, 8960)   : W_qkv^T split
//   blocks [8960, 9216)   : W_out^T split
//   blocks [9216, 10240)  : bias gather * log2e
// ---------------------------------------------------------------------------
__global__ void __launch_bounds__(256) prep_all(
    const float* __restrict__ x, const float* __restrict__ wq,
    const float* __restrict__ wo, const float* __restrict__ table,
    const int* __restrict__ rel_index)
{
    const int bid = blockIdx.x;
    if (bid < 8192) {
        size_t i = (size_t)bid * 256 + threadIdx.x;
        float4 v = ((const float4*)x)[i];
        uint32_t h01 = packh(v.x, v.y), h23 = packh(v.z, v.w);
        float2 a = unpackh(h01), b = unpackh(h23);
        ((uint2*)g_xh)[i] = make_uint2(h01, h23);
        ((uint2*)g_xl)[i] = make_uint2(packh(v.x - a.x, v.y - a.y),
                                       packh(v.z - b.x, v.w - b.y));
    } else if (bid < 8960) {
        int i = (bid - 8192) * 256 + threadIdx.x;
        int k = i / QKVC, n = i % QKVC;
        float v = wq[i];
        __half h = __float2half_rn(v);
        g_wqh[n * INP + k] = h;
        g_wql[n * INP + k] = __float2half_rn(v - __half2float(h));
    } else if (bid < 9216) {
        int i = (bid - 8960) * 256 + threadIdx.x;
        int k = i >> 8, n = i & 255;
        float v = wo[i];
        __half h = __float2half_rn(v);
        g_woh[n * INNER + k] = h;
        g_wol[n * INNER + k] = __float2half_rn(v - __half2float(h));
    } else {
        int tI = (bid - 9216) * 256 + threadIdx.x;
        int i = tI >> 8;
        int j = (tI & 255) * 4;
        int4 idx = *(const int4*)&rel_index[i * Nn + j];
        int id[4] = {idx.x, idx.y, idx.z, idx.w};
        float vals[4][8];
        #pragma unroll
        for (int jj = 0; jj < 4; jj++) {
            const float4* tp = (const float4*)(table + (size_t)id[jj] * 8);
            float4 a = tp[0], b = tp[1];
            vals[jj][0] = a.x; vals[jj][1] = a.y; vals[jj][2] = a.z; vals[jj][3] = a.w;
            vals[jj][4] = b.x; vals[jj][5] = b.y; vals[jj][6] = b.z; vals[jj][7] = b.w;
        }
        #pragma unroll
        for (int h = 0; h < 8; h++) {
            uint2 o;
            o.x = packh(vals[0][h] * LOG2E, vals[1][h] * LOG2E);
            o.y = packh(vals[2][h] * LOG2E, vals[3][h] * LOG2E);
            *(uint2*)&g_bias[((size_t)h * Nn + i) * Nn + j] = o;
        }
    }
}

// ---------------------------------------------------------------------------
// Kernel 1: QKV GEMM (round-11 proven): q/k 1-term, v 3-term fp16.
// ---------------------------------------------------------------------------
__global__ void __launch_bounds__(128) qkv_gemm_tc() {
    __shared__ __half Ah[2][64][40], Al[2][64][40];
    __shared__ __half Bh[2][64][40], Bl[2][64][40];

    const int m0 = blockIdx.x * 64;
    const int n0 = blockIdx.y * 64;
    const int tid = threadIdx.x;
    const int warp = tid >> 5, lane = tid & 31;
    const int g = lane >> 2, t = lane & 3;
    const int lsel = lane >> 3, lr = lane & 7;
    const int wy = warp >> 1, wx = warp & 1;
    const int tpart = n0 >> 8;
    const bool isv = (tpart == 2);

    auto issue = [&](int k0, int buf) {
        #pragma unroll
        for (int i = tid; i < 256; i += 128) {
            const int r = i >> 2, c = (i & 3) * 8;
            cpa16(&Ah[buf][r][c], &g_xh[(size_t)(m0 + r) * INP + k0 + c]);
            cpa16(&Bh[buf][r][c], &g_wqh[(size_t)(n0 + r) * INP + k0 + c]);
            if (isv) {
                cpa16(&Al[buf][r][c], &g_xl[(size_t)(m0 + r) * INP + k0 + c]);
                cpa16(&Bl[buf][r][c], &g_wql[(size_t)(n0 + r) * INP + k0 + c]);
            }
        }
        CP_COMMIT;
    };

    float c4[2][4][4] = {};
    issue(0, 0);

    for (int kk = 0; kk < 8; kk++) {
        const int buf = kk & 1;
        CP_WAIT0;
        __syncthreads();
        if (kk < 7) issue((kk + 1) * 32, buf ^ 1);

        #pragma unroll
        for (int kt = 0; kt < 2; kt++) {
            uint32_t ah[2][4], al[2][4];
            #pragma unroll
            for (int mi = 0; mi < 2; mi++) {
                const int r = wy * 32 + mi * 16 + (lsel & 1) * 8 + lr;
                const int cc = kt * 16 + (lsel >> 1) * 8;
                ldsm4(ah[mi][0], ah[mi][1], ah[mi][2], ah[mi][3], &Ah[buf][r][cc]);
                if (isv)
                    ldsm4(al[mi][0], al[mi][1], al[mi][2], al[mi][3], &Al[buf][r][cc]);
            }
            #pragma unroll
            for (int ntp = 0; ntp < 2; ntp++) {
                const int r = wx * 32 + ntp * 16 + (lsel >> 1) * 8 + lr;
                const int cc = kt * 16 + (lsel & 1) * 8;
                uint32_t b0, b1, b2, b3;
                ldsm4(b0, b1, b2, b3, &Bh[buf][r][cc]);
                if (isv) {
                    uint32_t e0, e1, e2, e3;
                    ldsm4(e0, e1, e2, e3, &Bl[buf][r][cc]);
                    #pragma unroll
                    for (int mi = 0; mi < 2; mi++) {
                        mma4(c4[mi][2*ntp],   ah[mi], b0, b1);
                        mma4(c4[mi][2*ntp],   ah[mi], e0, e1);
                        mma4(c4[mi][2*ntp],   al[mi], b0, b1);
                        mma4(c4[mi][2*ntp+1], ah[mi], b2, b3);
                        mma4(c4[mi][2*ntp+1], ah[mi], e2, e3);
                        mma4(c4[mi][2*ntp+1], al[mi], b2, b3);
                    }
                } else {
                    #pragma unroll
                    for (int mi = 0; mi < 2; mi++) {
                        mma4(c4[mi][2*ntp],   ah[mi], b0, b1);
                        mma4(c4[mi][2*ntp+1], ah[mi], b2, b3);
                    }
                }
            }
        }
    }

    const float qscale = 0.1767766952966369f * LOG2E;
    #pragma unroll
    for (int mi = 0; mi < 2; mi++) {
        #pragma unroll
        for (int ni = 0; ni < 4; ni++) {
            const int col = n0 + wx * 32 + ni * 8 + 2 * t;
            const int ci = col & 255;
            const int h = ci >> 5, d = ci & 31;
            #pragma unroll
            for (int half = 0; half < 2; half++) {
                const int r = m0 + wy * 32 + mi * 16 + g + half * 8;
                const int b = r >> 10, n = r & 1023;
                float v0 = c4[mi][ni][half * 2 + 0];
                float v1 = c4[mi][ni][half * 2 + 1];
                if (tpart == 0) {
                    v0 *= qscale; v1 *= qscale;
                    const size_t idx = (((size_t)(b * Hh + h)) * Nn + n) * Dd + d;
                    *(uint32_t*)&g_qh[idx] = packh(v0, v1);
                } else if (tpart == 1) {
                    const size_t idx = (((size_t)(b * Hh + h)) * Nn + n) * Dd + d;
                    *(uint32_t*)&g_kh[idx] = packh(v0, v1);
                } else {
                    uint32_t hi = packh(v0, v1);
                    float2 hf = unpackh(hi);
                    uint32_t lo = packh(v0 - hf.x, v1 - hf.y);
                    const size_t tv = (((size_t)(b * Hh + h)) * Dd + d) * Nn + n;
                    __half2 hb = *reinterpret_cast<__half2*>(&hi);
                    __half2 lb = *reinterpret_cast<__half2*>(&lo);
                    g_vth[tv] = hb.x;  g_vth[tv + Nn] = hb.y;
                    g_vtl[tv] = lb.x;  g_vtl[tv + Nn] = lb.y;
                }
            }
        }
    }
}

// ---------------------------------------------------------------------------
// Kernel 2: flash attention (round-11 proven, 401us config):
//   S = Qh*Kh (1-term); P = ex2.f16x2(pack(S) + bias_h2); PV 2-term;
//   row sums via ones-column MMA. 64 q-rows/CTA, 4 warps, dbuf cp.async.
//   per-buf: Kh@0 [64][40] | Vh@5120 [32][72] | Vl@9728; stride 14336
// ---------------------------------------------------------------------------
__global__ void __launch_bounds__(128) attn_tc() {
    __shared__ __align__(16) char smr[2 * 14336];

    const int qt = blockIdx.x, h = blockIdx.y, b = blockIdx.z;
    const int m0 = qt * 64;
    const int tid = threadIdx.x, warp = tid >> 5, lane = tid & 31;
    const int g = lane >> 2, t = lane & 3;
    const int lsel = lane >> 3, lr = lane & 7;

    const size_t head = (size_t)(b * Hh + h);
    const size_t qoff = (head * Nn + m0) * Dd;
    const size_t kbase = head * Nn * Dd;
    const size_t vbase = head * Dd * Nn;
    const size_t bbase = ((size_t)h * Nn + (m0 + warp * 16)) * Nn;

    typedef __half (*row40)[40];
    typedef __half (*row72)[72];
    auto KH = [&](int buf) { return (row40)(smr + buf * 14336); };
    auto VH = [&](int buf) { return (row72)(smr + buf * 14336 + 5120); };
    auto VL = [&](int buf) { return (row72)(smr + buf * 14336 + 9728); };
    row40 Qh = (row40)(smr + 14336);   // Q staging aliases buf1 Kh

    auto issue = [&](int j0, int buf) {
        row40 kh = KH(buf);
        row72 vh = VH(buf); row72 vl = VL(buf);
        #pragma unroll
        for (int i = tid; i < 256; i += 128) {
            const int r = i >> 2, c = (i & 3) * 8;
            cpa16(&kh[r][c], &g_kh[kbase + (size_t)(j0 + r) * Dd + c]);
        }
        #pragma unroll
        for (int i = tid; i < 256; i += 128) {
            const int r = i >> 3, c = (i & 7) * 8;
            cpa16(&vh[r][c], &g_vth[vbase + (size_t)r * Nn + j0 + c]);
            cpa16(&vl[r][c], &g_vtl[vbase + (size_t)r * Nn + j0 + c]);
        }
        CP_COMMIT;
    };

    issue(0, 0);

    {   // stage Q-hi into alias region
        const int row = tid & 63;
        const int u = (tid >> 6) * 2;
        const uint4* sh = (const uint4*)&g_qh[qoff + (size_t)row * Dd];
        ((uint4*)&Qh[row][0])[u]     = sh[u];
        ((uint4*)&Qh[row][0])[u + 1] = sh[u + 1];
    }
    __syncthreads();

    uint32_t qfh[2][4];
    #pragma unroll
    for (int kt = 0; kt < 2; kt++) {
        const int r = warp * 16 + (lsel & 1) * 8 + lr;
        const int cc = kt * 16 + (lsel >> 1) * 8;
        ldsm4(qfh[kt][0], qfh[kt][1], qfh[kt][2], qfh[kt][3], &Qh[r][cc]);
    }

    float o[4][4] = {};
    float lacc[4] = {};   // ones-column MMA accumulator: [0]=row g, [2]=row g+8

    for (int jt = 0; jt < 16; jt++) {
        const int buf = jt & 1;
        CP_WAIT0;
        __syncthreads();
        if (jt < 15) issue((jt + 1) * 64, buf ^ 1);

        row40 kh = KH(buf);
        row72 vh = VH(buf); row72 vl = VL(buf);

        float sc[8][4];
        #pragma unroll
        for (int nt = 0; nt < 8; nt++)
            sc[nt][0] = sc[nt][1] = sc[nt][2] = sc[nt][3] = 0.f;

        // S = Qh * Kh (1-term fp16)
        #pragma unroll
        for (int kt = 0; kt < 2; kt++) {
            const int cc = kt * 16 + (lsel & 1) * 8;
            #pragma unroll
            for (int ntp = 0; ntp < 4; ntp++) {
                const int r = ntp * 16 + (lsel >> 1) * 8 + lr;
                uint32_t h0, h1, h2, h3;
                ldsm4(h0, h1, h2, h3, &kh[r][cc]);
                mma4(sc[2*ntp],   qfh[kt], h0, h1);
                mma4(sc[2*ntp+1], qfh[kt], h2, h3);
            }
        }

        // softmax, f16x2: pack(S) + bias_h2 -> ex2.f16x2 -> P
        const int j0 = jt * 64;
        uint32_t pp[8][2];
        #pragma unroll
        for (int nt = 0; nt < 8; nt++) {
            const int j = j0 + nt * 8 + 2 * t;
            uint32_t u0 = *(const uint32_t*)&g_bias[bbase + (size_t)g * Nn + j];
            uint32_t u1 = *(const uint32_t*)&g_bias[bbase + (size_t)(g + 8) * Nn + j];
            pp[nt][0] = ex2h2(hadd2u(packh(sc[nt][0], sc[nt][1]), u0));
            pp[nt][1] = ex2h2(hadd2u(packh(sc[nt][2], sc[nt][3]), u1));
        }

        // O += P V (2-term) + row-sum via ones-column MMA
        #pragma unroll
        for (int kt2 = 0; kt2 < 4; kt2++) {
            uint32_t pah[4];
            pah[0] = pp[2*kt2][0];
            pah[1] = pp[2*kt2][1];
            pah[2] = pp[2*kt2+1][0];
            pah[3] = pp[2*kt2+1][1];

            const int cc = kt2 * 16 + (lsel & 1) * 8;
            const int rA = (lsel >> 1) * 8 + lr;
            uint32_t v0, v1, v2, v3, w0, w1, w2, w3;
            ldsm4(v0, v1, v2, v3, &vh[rA][cc]);
            ldsm4(w0, w1, w2, w3, &vl[rA][cc]);
            mma4(o[0], pah, v0, v1); mma4(o[0], pah, w0, w1);
            mma4(o[1], pah, v2, v3); mma4(o[1], pah, w2, w3);
            ldsm4(v0, v1, v2, v3, &vh[16 + rA][cc]);
            ldsm4(w0, w1, w2, w3, &vl[16 + rA][cc]);
            mma4(o[2], pah, v0, v1); mma4(o[2], pah, w0, w1);
            mma4(o[3], pah, v2, v3); mma4(o[3], pah, w2, w3);
            mma4(lacc, pah, ONES_H2, ONES_H2);   // row sums
        }
    }

    const float inv0 = 1.f / lacc[0], inv1 = 1.f / lacc[2];

    #pragma unroll
    for (int nv = 0; nv < 4; nv++) {
        const int colb = h * 32 + nv * 8 + 2 * t;
        const int r0 = m0 + warp * 16 + g;
        const size_t i0 = ((size_t)b * Nn + r0) * INNER + colb;
        const size_t i1 = i0 + (size_t)8 * INNER;
        *(uint32_t*)&g_oh[i0] = packh(o[nv][0] * inv0, o[nv][1] * inv0);
        *(uint32_t*)&g_oh[i1] = packh(o[nv][2] * inv1, o[nv][3] * inv1);
    }
}

// ---------------------------------------------------------------------------
// Kernel 3: out-projection GEMM (round-11 proven), 2-term: Oh*(Wh + Wl) + b
// ---------------------------------------------------------------------------
__global__ void __launch_bounds__(128) out_gemm_tc(
    const float* __restrict__ bias, float* __restrict__ out)
{
    __shared__ __half Ah[2][64][40];
    __shared__ __half Bh[2][64][40], Bl[2][64][40];

    const int m0 = blockIdx.x * 64;
    const int n0 = blockIdx.y * 64;
    const int tid = threadIdx.x;
    const int warp = tid >> 5, lane = tid & 31;
    const int g = lane >> 2, t = lane & 3;
    const int lsel = lane >> 3, lr = lane & 7;
    const int wy = warp >> 1, wx = warp & 1;

    auto issue = [&](int k0, int buf) {
        #pragma unroll
        for (int i = tid; i < 256; i += 128) {
            const int r = i >> 2, c = (i & 3) * 8;
            cpa16(&Ah[buf][r][c], &g_oh[(size_t)(m0 + r) * INNER + k0 + c]);
            cpa16(&Bh[buf][r][c], &g_woh[(size_t)(n0 + r) * INNER + k0 + c]);
            cpa16(&Bl[buf][r][c], &g_wol[(size_t)(n0 + r) * INNER + k0 + c]);
        }
        CP_COMMIT;
    };

    float c4[2][4][4] = {};
    issue(0, 0);

    for (int kk = 0; kk < 8; kk++) {
        const int buf = kk & 1;
        CP_WAIT0;
        __syncthreads();
        if (kk < 7) issue((kk + 1) * 32, buf ^ 1);

        #pragma unroll
        for (int kt = 0; kt < 2; kt++) {
            uint32_t ah[2][4];
            #pragma unroll
            for (int mi = 0; mi < 2; mi++) {
                const int r = wy * 32 + mi * 16 + (lsel & 1) * 8 + lr;
                const int cc = kt * 16 + (lsel >> 1) * 8;
                ldsm4(ah[mi][0], ah[mi][1], ah[mi][2], ah[mi][3], &Ah[buf][r][cc]);
            }
            #pragma unroll
            for (int ntp = 0; ntp < 2; ntp++) {
                const int r = wx * 32 + ntp * 16 + (lsel >> 1) * 8 + lr;
                const int cc = kt * 16 + (lsel & 1) * 8;
                uint32_t b0, b1, b2, b3, e0, e1, e2, e3;
                ldsm4(b0, b1, b2, b3, &Bh[buf][r][cc]);
                ldsm4(e0, e1, e2, e3, &Bl[buf][r][cc]);
                #pragma unroll
                for (int mi = 0; mi < 2; mi++) {
                    mma4(c4[mi][2*ntp],   ah[mi], b0, b1);
                    mma4(c4[mi][2*ntp],   ah[mi], e0, e1);
                    mma4(c4[mi][2*ntp+1], ah[mi], b2, b3);
                    mma4(c4[mi][2*ntp+1], ah[mi], e2, e3);
                }
            }
        }
    }

    #pragma unroll
    for (int mi = 0; mi < 2; mi++) {
        #pragma unroll
        for (int ni = 0; ni < 4; ni++) {
            const int col = n0 + wx * 32 + ni * 8 + 2 * t;
            const float b0 = bias[col], b1 = bias[col + 1];
            #pragma unroll
            for (int half = 0; half < 2; half++) {
                const int r = m0 + wy * 32 + mi * 16 + g + half * 8;
                float2 v = make_float2(c4[mi][ni][half * 2 + 0] + b0,
                                       c4[mi][ni][half * 2 + 1] + b1);
                *(float2*)&out[(size_t)r * OUP + col] = v;
            }
        }
    }
}

// ---------------------------------------------------------------------------
// Launch
// ---------------------------------------------------------------------------
extern "C" void kernel_launch(void* const* d_in, const int* in_sizes, int n_in,
                              void* d_out, int out_size)
{
    const float* x          = (const float*)d_in[0];
    const float* W_qkv      = (const float*)d_in[1];
    const float* bias_table = (const float*)d_in[2];
    const float* W_out      = (const float*)d_in[3];
    const float* b_out      = (const float*)d_in[4];
    const int*   rel_index  = (const int*)d_in[5];
    float* out = (float*)d_out;
    (void)in_sizes; (void)n_in; (void)out_size;

    prep_all<<<10240, 256>>>(x, W_qkv, W_out, bias_table, rel_index);

    qkv_gemm_tc<<<dim3(NTOK / 64, QKVC / 64), 128>>>();          // (512, 12)
    attn_tc<<<dim3(Nn / 64, Hh, Bc), 128>>>();                   // (16, 8, 32)
    out_gemm_tc<<<dim3(NTOK / 64, OUP / 64), 128>>>(b_out, out); // (512, 4)
}